// round 2
// baseline (speedup 1.0000x reference)
#include <cuda_runtime.h>

#define BQ    32
#define NN    512
#define MM    512
#define DFD   64
#define NDIAG 1023          // diagonals d = 2 .. 1024 -> slot (d-2) in [0, 1022]
#define BIGV  1e10f

// Diagonal-major distance scratch: g_D[b][(i+j)][i] for 0-based i,j.
__device__ float g_D[(size_t)BQ * NDIAG * NN];

// ---------------------------------------------------------------------------
// Kernel 1: pairwise squared distances, written in anti-diagonal layout.
// Grid: (8, 8, 32) tiles of 64x64; 256 threads; 4x4 register tile per thread.
// ---------------------------------------------------------------------------
__global__ void dist_kernel(const float* __restrict__ X,
                            const float* __restrict__ Y) {
    __shared__ float sm[2 * 64 * 65];   // Xs | Ys, padded pitch 65
    float* Xs = sm;
    float* Ys = sm + 64 * 65;

    const int b  = blockIdx.z;
    const int i0 = blockIdx.y * 64;
    const int j0 = blockIdx.x * 64;
    const int tid = threadIdx.x;

    const float* Xb = X + ((size_t)b * NN + i0) * DFD;
    const float* Yb = Y + ((size_t)b * MM + j0) * DFD;

    #pragma unroll
    for (int idx = tid; idx < 64 * 64; idx += 256) {
        int r = idx >> 6, c = idx & 63;
        Xs[r * 65 + c] = Xb[r * 64 + c];
        Ys[r * 65 + c] = Yb[r * 64 + c];
    }
    __syncthreads();

    const int ti = (tid >> 4) * 4;
    const int tj = (tid & 15) * 4;

    float acc[4][4];
    #pragma unroll
    for (int u = 0; u < 4; u++)
        #pragma unroll
        for (int v = 0; v < 4; v++) acc[u][v] = 0.f;

    #pragma unroll 4
    for (int k = 0; k < DFD; k++) {
        float xa[4], yb[4];
        #pragma unroll
        for (int u = 0; u < 4; u++) xa[u] = Xs[(ti + u) * 65 + k];
        #pragma unroll
        for (int v = 0; v < 4; v++) yb[v] = Ys[(tj + v) * 65 + k];
        #pragma unroll
        for (int u = 0; u < 4; u++)
            #pragma unroll
            for (int v = 0; v < 4; v++) {
                float dd = xa[u] - yb[v];
                acc[u][v] = fmaf(dd, dd, acc[u][v]);
            }
    }
    __syncthreads();

    // Stage tile (pitch 66 -> conflict-free diagonal reads).
    float* Dt = sm;
    #pragma unroll
    for (int u = 0; u < 4; u++)
        #pragma unroll
        for (int v = 0; v < 4; v++)
            Dt[(ti + u) * 66 + (tj + v)] = acc[u][v];
    __syncthreads();

    // Coalesced diagonal-major writeback.
    const int warp = tid >> 5, lane = tid & 31;
    const size_t base = (size_t)b * NDIAG * NN;
    for (int dl = warp; dl < 127; dl += 8) {
        int lo = dl - 63; if (lo < 0) lo = 0;
        int hi = dl;      if (hi > 63) hi = 63;
        for (int ii = lo + lane; ii <= hi; ii += 32) {
            int gi = i0 + ii;
            int gj = j0 + dl - ii;
            g_D[base + (size_t)(gi + gj) * NN + gi] = Dt[ii * 66 + (dl - ii)];
        }
    }
}

// ---------------------------------------------------------------------------
// One soft-min cell: R = D + softmin(a, b, c).
// softmin = m - log(1 + e^(m-mid) + e^(m-top)) with m<=mid<=top (sorted).
// ---------------------------------------------------------------------------
__device__ __forceinline__ float cell(float a, float bb, float c,
                                      float Dv, bool valid) {
    const float mn1 = fminf(a, bb), mx1 = fmaxf(a, bb);
    const float m   = fminf(mn1, c);
    const float mid = fminf(mx1, fmaxf(mn1, c));
    const float top = fmaxf(mx1, c);
    const float s   = 1.0f + __expf(m - mid) + __expf(m - top);
    return valid ? (Dv + m - __logf(s)) : BIGV;
}

// ---------------------------------------------------------------------------
// Kernel 2: register-resident wavefront soft-DTW. One CTA per batch.
// 256 threads (8 warps); thread t owns rows i_lo = 2t+1, i_hi = 2t+2.
// Cross-thread comm: one shfl_up per iter (d-2 neighbor is the retained
// d-1 shuffle from the previous iter). Cross-warp: 3-deep SMEM edge ring.
// D prefetched 3 diagonals ahead as float2.
// ---------------------------------------------------------------------------
__global__ void __launch_bounds__(256, 1)
dp_kernel(const int* __restrict__ X_len, const int* __restrict__ Y_len,
          float* __restrict__ out) {
    __shared__ float sm_edge[3][8];

    const int b    = blockIdx.x;
    const int tid  = threadIdx.x;
    const int w    = tid >> 5;
    const int lane = tid & 31;
    const int i_lo = 2 * tid + 1;
    const int i_hi = i_lo + 1;

    const int xl  = X_len[b];
    const int tot = xl + Y_len[b];

    if (tid < 24) ((float*)sm_edge)[tid] = BIGV;

    // D pointer: thread t reads positions (2t, 2t+1) of each diagonal slot.
    const float2* Dp = (const float2*)(g_D + (size_t)b * NDIAG * NN) + tid;

    // Prefetch slots 0,1,2 (diagonals d = 2,3,4).
    float2 Dc  = Dp[0];
    float2 Dn1 = Dp[256];
    float2 Dn2 = Dp[512];

    float r1_lo = BIGV, r1_hi = BIGV;   // R on diagonal d-1
    float r2_lo = BIGV;                 // R on diagonal d-2 (row i_lo)
    float an = (tid == 0) ? 0.0f : BIGV;  // R[d-2][i_lo - 1] (neighbor)

    __syncthreads();

    int rc = 2, rm1 = 1;                // d%3, (d-1)%3 at d=2

    for (int d = 2; d <= NN + MM; ++d) {
        // Neighbor's R[d-1][i_lo - 1].
        float tmp = __shfl_up_sync(0xffffffffu, r1_hi, 1);
        if (lane == 0)
            tmp = (w == 0) ? BIGV : sm_edge[rm1][w - 1];

        const bool v_lo = (unsigned)(d - i_lo - 1) < (unsigned)MM;
        const bool v_hi = (unsigned)(d - i_hi - 1) < (unsigned)MM;

        const float cur_lo = cell(an,    tmp,   r1_lo, Dc.x, v_lo);
        const float cur_hi = cell(r2_lo, r1_lo, r1_hi, Dc.y, v_hi);

        if (d == tot) {
            if (xl == i_lo)      out[b] = cur_lo;
            else if (xl == i_hi) out[b] = cur_hi;
        }
        if (lane == 31) sm_edge[rc][w] = cur_hi;

        // Rotate state.
        r2_lo = r1_lo;
        r1_lo = cur_lo;
        r1_hi = cur_hi;
        an    = tmp;

        // Rotate D prefetch pipeline (load slot d+1 for diagonal d+3).
        Dc  = Dn1;
        Dn1 = Dn2;
        int slot = d + 1; if (slot > NDIAG - 1) slot = NDIAG - 1;
        Dn2 = Dp[(size_t)slot * 256];

        rm1 = rc;
        rc  = (rc == 2) ? 0 : rc + 1;

        __syncthreads();
    }
}

// ---------------------------------------------------------------------------
extern "C" void kernel_launch(void* const* d_in, const int* in_sizes, int n_in,
                              void* d_out, int out_size) {
    const float* X     = (const float*)d_in[0];
    const float* Y     = (const float*)d_in[1];
    const int*   X_len = (const int*)d_in[2];
    const int*   Y_len = (const int*)d_in[3];
    float*       out   = (float*)d_out;

    dist_kernel<<<dim3(8, 8, BQ), 256>>>(X, Y);
    dp_kernel<<<BQ, 256>>>(X_len, Y_len, out);
}

// round 3
// speedup vs baseline: 1.3817x; 1.3817x over previous
#include <cuda_runtime.h>

#define BQ    32
#define NN    512
#define MM    512
#define DFD   64
#define NDIAG 1023          // diagonals d = 2 .. 1024 -> slot (d-2) in [0, 1022]
#define BIGV  1e10f
#define TCH   8             // diagonals per sync chunk

// Diagonal-major distance scratch: g_D[b][(i+j)][i] for 0-based i,j.
__device__ float g_D[(size_t)BQ * NDIAG * NN];

// ---------------------------------------------------------------------------
// Kernel 1: pairwise squared distances, written in anti-diagonal layout.
// ---------------------------------------------------------------------------
__global__ void dist_kernel(const float* __restrict__ X,
                            const float* __restrict__ Y) {
    __shared__ float sm[2 * 64 * 65];
    float* Xs = sm;
    float* Ys = sm + 64 * 65;

    const int b  = blockIdx.z;
    const int i0 = blockIdx.y * 64;
    const int j0 = blockIdx.x * 64;
    const int tid = threadIdx.x;

    const float* Xb = X + ((size_t)b * NN + i0) * DFD;
    const float* Yb = Y + ((size_t)b * MM + j0) * DFD;

    #pragma unroll
    for (int idx = tid; idx < 64 * 64; idx += 256) {
        int r = idx >> 6, c = idx & 63;
        Xs[r * 65 + c] = Xb[r * 64 + c];
        Ys[r * 65 + c] = Yb[r * 64 + c];
    }
    __syncthreads();

    const int ti = (tid >> 4) * 4;
    const int tj = (tid & 15) * 4;

    float acc[4][4];
    #pragma unroll
    for (int u = 0; u < 4; u++)
        #pragma unroll
        for (int v = 0; v < 4; v++) acc[u][v] = 0.f;

    #pragma unroll 4
    for (int k = 0; k < DFD; k++) {
        float xa[4], yb[4];
        #pragma unroll
        for (int u = 0; u < 4; u++) xa[u] = Xs[(ti + u) * 65 + k];
        #pragma unroll
        for (int v = 0; v < 4; v++) yb[v] = Ys[(tj + v) * 65 + k];
        #pragma unroll
        for (int u = 0; u < 4; u++)
            #pragma unroll
            for (int v = 0; v < 4; v++) {
                float dd = xa[u] - yb[v];
                acc[u][v] = fmaf(dd, dd, acc[u][v]);
            }
    }
    __syncthreads();

    float* Dt = sm;                       // pitch 66 -> conflict-free diagonals
    #pragma unroll
    for (int u = 0; u < 4; u++)
        #pragma unroll
        for (int v = 0; v < 4; v++)
            Dt[(ti + u) * 66 + (tj + v)] = acc[u][v];
    __syncthreads();

    const int warp = tid >> 5, lane = tid & 31;
    const size_t base = (size_t)b * NDIAG * NN;
    for (int dl = warp; dl < 127; dl += 8) {
        int lo = dl - 63; if (lo < 0) lo = 0;
        int hi = dl;      if (hi > 63) hi = 63;
        for (int ii = lo + lane; ii <= hi; ii += 32) {
            int gi = i0 + ii;
            int gj = j0 + dl - ii;
            g_D[base + (size_t)(gi + gj) * NN + gi] = Dt[ii * 66 + (dl - ii)];
        }
    }
}

// ---------------------------------------------------------------------------
// Soft-min cell: R = D + softmin(a, b, c)  (gamma=1, warp=0).
// ---------------------------------------------------------------------------
__device__ __forceinline__ float cell(float a, float bb, float c,
                                      float Dv, bool valid) {
    const float mn1 = fminf(a, bb), mx1 = fmaxf(a, bb);
    const float m   = fminf(mn1, c);
    const float mid = fminf(mx1, fmaxf(mn1, c));
    const float top = fmaxf(mx1, c);
    const float s   = 1.0f + __expf(m - mid) + __expf(m - top);
    return valid ? (Dv + m - __logf(s)) : BIGV;
}

// ---------------------------------------------------------------------------
// Kernel 2: barrier-free warp-pipelined wavefront. One CTA per batch.
// 8 warps x 64 rows (thread t owns rows 2t+1, 2t+2). Warps are skewed by one
// 8-diagonal chunk; cross-warp edges go through a full SMEM edge history with
// a per-warp progress counter (poll + membar.cta once per chunk).
// ---------------------------------------------------------------------------
__global__ void __launch_bounds__(256, 1)
dp_kernel(const int* __restrict__ X_len, const int* __restrict__ Y_len,
          float* __restrict__ out) {
    __shared__ float edge[8][1032];    // edge[w][d] = R[d][64(w+1)]
    __shared__ int   prog[8];          // last diagonal whose edge is published
    volatile int* vprog = prog;

    const int b    = blockIdx.x;
    const int tid  = threadIdx.x;
    const int w    = tid >> 5;
    const int lane = tid & 31;
    const int i_lo = 2 * tid + 1;
    const int i_hi = i_lo + 1;

    const int xl  = X_len[b];
    const int tot = xl + Y_len[b];

    if (tid < 8) { prog[tid] = 1; edge[tid][0] = BIGV; edge[tid][1] = BIGV; }
    __syncthreads();                    // the only CTA barrier

    const float2* Dp = (const float2*)(g_D + (size_t)b * NDIAG * NN) + tid;
    float2 Dc  = Dp[0];
    float2 Dn1 = Dp[256];
    float2 Dn2 = Dp[512];

    float r1_lo = BIGV, r1_hi = BIGV, r2_lo = BIGV;
    float an = (tid == 0) ? 0.0f : BIGV;   // R[d-2][i_lo-1]

    // 128 chunks of 8 diagonals: d = 2 .. 1025 (1025 is a dummy, all-invalid).
    for (int d0 = 2; d0 <= 1018; d0 += TCH) {
        if (w > 0) {
            const int needed = d0 + TCH - 2;        // max (d-1) in this chunk
            while (vprog[w - 1] < needed) { }
            __threadfence_block();                  // acquire
        }

        #pragma unroll
        for (int k = 0; k < TCH; ++k) {
            const int d = d0 + k;

            float tmp = __shfl_up_sync(0xffffffffu, r1_hi, 1);
            if (lane == 0)
                tmp = (w == 0) ? BIGV : edge[w - 1][d - 1];

            const bool v_lo = (unsigned)(d - i_lo - 1) < (unsigned)MM;
            const bool v_hi = (unsigned)(d - i_hi - 1) < (unsigned)MM;

            const float cur_lo = cell(an,    tmp,   r1_lo, Dc.x, v_lo);
            const float cur_hi = cell(r2_lo, r1_lo, r1_hi, Dc.y, v_hi);

            if (d == tot) {
                if (xl == i_lo)      out[b] = cur_lo;
                else if (xl == i_hi) out[b] = cur_hi;
            }
            if (lane == 31) edge[w][d] = cur_hi;

            r2_lo = r1_lo;
            r1_lo = cur_lo;
            r1_hi = cur_hi;
            an    = tmp;

            Dc  = Dn1;
            Dn1 = Dn2;
            int s = d + 1; if (s > NDIAG - 1) s = NDIAG - 1;
            Dn2 = Dp[(size_t)s * 256];
        }

        if (w < 7) {
            __threadfence_block();                  // release
            if (lane == 31) vprog[w] = d0 + TCH - 1;
        }
    }
}

// ---------------------------------------------------------------------------
extern "C" void kernel_launch(void* const* d_in, const int* in_sizes, int n_in,
                              void* d_out, int out_size) {
    const float* X     = (const float*)d_in[0];
    const float* Y     = (const float*)d_in[1];
    const int*   X_len = (const int*)d_in[2];
    const int*   Y_len = (const int*)d_in[3];
    float*       out   = (float*)d_out;

    dist_kernel<<<dim3(8, 8, BQ), 256>>>(X, Y);
    dp_kernel<<<BQ, 256>>>(X_len, Y_len, out);
}

// round 4
// speedup vs baseline: 1.8571x; 1.3441x over previous
#include <cuda_runtime.h>

#define BQ    32
#define NN    512
#define MM    512
#define DFD   64
#define NDIAG 1023          // real diagonals d = 2 .. 1024 -> slot (d-2)
#define NDPAD 1040          // padded (zero-init) so prefetch never clamps
#define BIGV  1e10f
#define TCH   8             // diagonals per sync chunk

// Diagonal-major distance scratch: g_D[b][(i+j)][i] for 0-based i,j.
__device__ float g_D[(size_t)BQ * NDPAD * NN];

// ---------------------------------------------------------------------------
// Kernel 1: pairwise squared distances, written in anti-diagonal layout.
// ---------------------------------------------------------------------------
__global__ void dist_kernel(const float* __restrict__ X,
                            const float* __restrict__ Y) {
    __shared__ float sm[2 * 64 * 65];
    float* Xs = sm;
    float* Ys = sm + 64 * 65;

    const int b  = blockIdx.z;
    const int i0 = blockIdx.y * 64;
    const int j0 = blockIdx.x * 64;
    const int tid = threadIdx.x;

    const float* Xb = X + ((size_t)b * NN + i0) * DFD;
    const float* Yb = Y + ((size_t)b * MM + j0) * DFD;

    #pragma unroll
    for (int idx = tid; idx < 64 * 64; idx += 256) {
        int r = idx >> 6, c = idx & 63;
        Xs[r * 65 + c] = Xb[r * 64 + c];
        Ys[r * 65 + c] = Yb[r * 64 + c];
    }
    __syncthreads();

    const int ti = (tid >> 4) * 4;
    const int tj = (tid & 15) * 4;

    float acc[4][4];
    #pragma unroll
    for (int u = 0; u < 4; u++)
        #pragma unroll
        for (int v = 0; v < 4; v++) acc[u][v] = 0.f;

    #pragma unroll 4
    for (int k = 0; k < DFD; k++) {
        float xa[4], yb[4];
        #pragma unroll
        for (int u = 0; u < 4; u++) xa[u] = Xs[(ti + u) * 65 + k];
        #pragma unroll
        for (int v = 0; v < 4; v++) yb[v] = Ys[(tj + v) * 65 + k];
        #pragma unroll
        for (int u = 0; u < 4; u++)
            #pragma unroll
            for (int v = 0; v < 4; v++) {
                float dd = xa[u] - yb[v];
                acc[u][v] = fmaf(dd, dd, acc[u][v]);
            }
    }
    __syncthreads();

    float* Dt = sm;                       // pitch 66 -> conflict-free diagonals
    #pragma unroll
    for (int u = 0; u < 4; u++)
        #pragma unroll
        for (int v = 0; v < 4; v++)
            Dt[(ti + u) * 66 + (tj + v)] = acc[u][v];
    __syncthreads();

    const int warp = tid >> 5, lane = tid & 31;
    const size_t base = (size_t)b * NDPAD * NN;
    for (int dl = warp; dl < 127; dl += 8) {
        int lo = dl - 63; if (lo < 0) lo = 0;
        int hi = dl;      if (hi > 63) hi = 63;
        for (int ii = lo + lane; ii <= hi; ii += 32) {
            int gi = i0 + ii;
            int gj = j0 + dl - ii;
            g_D[base + (size_t)(gi + gj) * NN + gi] = Dt[ii * 66 + (dl - ii)];
        }
    }
}

// ---------------------------------------------------------------------------
// Soft-min cell: R = D + softmin(a, b, c)  (gamma=1, warp=0).
// ---------------------------------------------------------------------------
__device__ __forceinline__ float cell(float a, float bb, float c,
                                      float Dv, bool valid) {
    const float mn1 = fminf(a, bb), mx1 = fmaxf(a, bb);
    const float m   = fminf(mn1, c);
    const float mid = fminf(mx1, fmaxf(mn1, c));
    const float top = fmaxf(mx1, c);
    const float s   = 1.0f + __expf(m - mid) + __expf(m - top);
    return valid ? (Dv + m - __logf(s)) : BIGV;
}

// ---------------------------------------------------------------------------
// Kernel 2: barrier-free warp-pipelined wavefront, branchless inner loop.
// 8 warps x 64 rows (thread t owns rows 2t+1, 2t+2). Per 8-diagonal chunk:
// poll producer once, prefetch 8 edge values + next chunk's 8 float2 D loads
// into registers, then run 8 branch-free recurrence steps.
// ---------------------------------------------------------------------------
__global__ void __launch_bounds__(256, 1)
dp_kernel(const int* __restrict__ X_len, const int* __restrict__ Y_len,
          float* __restrict__ out) {
    __shared__ float edge[8][1032];    // edge[w][d] = R[d][64(w+1)]
    __shared__ int   prog[8];
    volatile int* vprog = prog;

    const int b    = blockIdx.x;
    const int tid  = threadIdx.x;
    const int w    = tid >> 5;
    const int lane = tid & 31;
    const int i_lo = 2 * tid + 1;
    const int i_hi = i_lo + 1;

    const int xl  = X_len[b];
    const int tot = xl + Y_len[b];
    const bool wantlo = (xl == i_lo);
    const bool wanthi = (xl == i_hi);
    const bool isl0  = (lane == 0);
    const bool isl31 = (lane == 31);

    if (tid < 8) { prog[tid] = 1; edge[tid][0] = BIGV; edge[tid][1] = BIGV; }
    __syncthreads();                    // the only CTA barrier

    const float2* Dp = (const float2*)(g_D + (size_t)b * NDPAD * NN) + tid;

    // Current chunk's D (slots 0..7 = diagonals 2..9).
    float2 Dc[TCH];
    #pragma unroll
    for (int k = 0; k < TCH; ++k) Dc[k] = Dp[(size_t)k * 256];

    float r1_lo = BIGV, r1_hi = BIGV, r2_lo = BIGV;
    float an  = (tid == 0) ? 0.0f : BIGV;
    float res = 0.0f;

    // 128 chunks: d = 2 .. 1025 (d=1025 is a dummy, all-invalid).
    for (int d0 = 2; d0 <= 1018; d0 += TCH) {
        // Prefetch next chunk's D (slots d0+6 .. d0+13; padded array).
        float2 Dn[TCH];
        #pragma unroll
        for (int k = 0; k < TCH; ++k)
            Dn[k] = Dp[(size_t)(d0 + 6 + k) * 256];

        // Acquire producer edges for this chunk, prefetch to registers.
        float e[TCH];
        if (w > 0) {
            const int needed = d0 + TCH - 2;
            while (vprog[w - 1] < needed) { }
            __threadfence_block();
            #pragma unroll
            for (int k = 0; k < TCH; ++k) e[k] = edge[w - 1][d0 - 1 + k];
        } else {
            #pragma unroll
            for (int k = 0; k < TCH; ++k) e[k] = BIGV;
        }

        #pragma unroll
        for (int k = 0; k < TCH; ++k) {
            const int d = d0 + k;

            float tmp = __shfl_up_sync(0xffffffffu, r1_hi, 1);
            tmp = isl0 ? e[k] : tmp;

            const bool v_lo = (unsigned)(d - i_lo - 1) < (unsigned)MM;
            const bool v_hi = (unsigned)(d - i_hi - 1) < (unsigned)MM;

            const float cur_lo = cell(an,    tmp,   r1_lo, Dc[k].x, v_lo);
            const float cur_hi = cell(r2_lo, r1_lo, r1_hi, Dc[k].y, v_hi);

            if (d == tot)
                res = wantlo ? cur_lo : (wanthi ? cur_hi : res);

            if (isl31) edge[w][d] = cur_hi;

            r2_lo = r1_lo;
            r1_lo = cur_lo;
            r1_hi = cur_hi;
            an    = tmp;
        }

        if (w < 7) {
            __threadfence_block();
            if (isl31) vprog[w] = d0 + TCH - 1;
        }

        #pragma unroll
        for (int k = 0; k < TCH; ++k) Dc[k] = Dn[k];
    }

    if (wantlo | wanthi) out[b] = res;
}

// ---------------------------------------------------------------------------
extern "C" void kernel_launch(void* const* d_in, const int* in_sizes, int n_in,
                              void* d_out, int out_size) {
    const float* X     = (const float*)d_in[0];
    const float* Y     = (const float*)d_in[1];
    const int*   X_len = (const int*)d_in[2];
    const int*   Y_len = (const int*)d_in[3];
    float*       out   = (float*)d_out;

    dist_kernel<<<dim3(8, 8, BQ), 256>>>(X, Y);
    dp_kernel<<<BQ, 256>>>(X_len, Y_len, out);
}

// round 5
// speedup vs baseline: 1.9222x; 1.0351x over previous
#include <cuda_runtime.h>
#include <cstdint>

#define BQ    32
#define NN    512
#define MM    512
#define DFD   64
#define NDIAG 1023          // real diagonals d = 2 .. 1024 -> slot (d-2)
#define NDPAD 1040          // padded so prefetch never clamps
#define BIGV  1e10f
#define TCH   8             // diagonals per sync chunk

// Diagonal-major distance scratch: g_D[b][(i+j)][i] for 0-based i,j.
__device__ float g_D[(size_t)BQ * NDPAD * NN];

// ---------------------------------------------------------------------------
// Scoped shared-memory release/acquire (no MEMBAR).
// ---------------------------------------------------------------------------
__device__ __forceinline__ uint32_t smem_u32(const void* p) {
    return (uint32_t)__cvta_generic_to_shared(p);
}
__device__ __forceinline__ void st_release_cta(uint32_t addr, int v) {
    asm volatile("st.release.cta.shared.b32 [%0], %1;" :: "r"(addr), "r"(v) : "memory");
}
__device__ __forceinline__ int ld_acquire_cta(uint32_t addr) {
    int v;
    asm volatile("ld.acquire.cta.shared.b32 %0, [%1];" : "=r"(v) : "r"(addr) : "memory");
    return v;
}

// ---------------------------------------------------------------------------
// Kernel 1: pairwise squared distances via Gram form, diagonal-major output.
// ---------------------------------------------------------------------------
__global__ void dist_kernel(const float* __restrict__ X,
                            const float* __restrict__ Y) {
    __shared__ float sm[2 * 64 * 65];
    __shared__ float xx[64], yy[64];
    float* Xs = sm;
    float* Ys = sm + 64 * 65;

    const int b  = blockIdx.z;
    const int i0 = blockIdx.y * 64;
    const int j0 = blockIdx.x * 64;
    const int tid = threadIdx.x;

    const float* Xb = X + ((size_t)b * NN + i0) * DFD;
    const float* Yb = Y + ((size_t)b * MM + j0) * DFD;

    #pragma unroll
    for (int idx = tid; idx < 64 * 64; idx += 256) {
        int r = idx >> 6, c = idx & 63;
        Xs[r * 65 + c] = Xb[r * 64 + c];
        Ys[r * 65 + c] = Yb[r * 64 + c];
    }
    __syncthreads();

    // Row norms (threads 0..63 -> xx, 64..127 -> yy).
    if (tid < 128) {
        const float* row = (tid < 64) ? &Xs[tid * 65] : &Ys[(tid - 64) * 65];
        float s = 0.f;
        #pragma unroll 8
        for (int k = 0; k < DFD; k++) s = fmaf(row[k], row[k], s);
        if (tid < 64) xx[tid] = s; else yy[tid - 64] = s;
    }
    __syncthreads();

    const int ti = (tid >> 4) * 4;
    const int tj = (tid & 15) * 4;

    float acc[4][4];
    #pragma unroll
    for (int u = 0; u < 4; u++)
        #pragma unroll
        for (int v = 0; v < 4; v++) acc[u][v] = 0.f;

    #pragma unroll 4
    for (int k = 0; k < DFD; k++) {
        float xa[4], yb[4];
        #pragma unroll
        for (int u = 0; u < 4; u++) xa[u] = Xs[(ti + u) * 65 + k];
        #pragma unroll
        for (int v = 0; v < 4; v++) yb[v] = Ys[(tj + v) * 65 + k];
        #pragma unroll
        for (int u = 0; u < 4; u++)
            #pragma unroll
            for (int v = 0; v < 4; v++)
                acc[u][v] = fmaf(xa[u], yb[v], acc[u][v]);
    }
    __syncthreads();

    float* Dt = sm;                       // pitch 66 -> conflict-free diagonals
    #pragma unroll
    for (int u = 0; u < 4; u++)
        #pragma unroll
        for (int v = 0; v < 4; v++)
            Dt[(ti + u) * 66 + (tj + v)] =
                fmaf(-2.0f, acc[u][v], xx[ti + u] + yy[tj + v]);
    __syncthreads();

    const int warp = tid >> 5, lane = tid & 31;
    const size_t base = (size_t)b * NDPAD * NN;
    for (int dl = warp; dl < 127; dl += 8) {
        int lo = dl - 63; if (lo < 0) lo = 0;
        int hi = dl;      if (hi > 63) hi = 63;
        for (int ii = lo + lane; ii <= hi; ii += 32) {
            int gi = i0 + ii;
            int gj = j0 + dl - ii;
            g_D[base + (size_t)(gi + gj) * NN + gi] = Dt[ii * 66 + (dl - ii)];
        }
    }
}

// ---------------------------------------------------------------------------
// Soft-min cell with presorted early pair (p<=q), late input arrives last:
// R = D + softmin(p, q, late).
// ---------------------------------------------------------------------------
__device__ __forceinline__ float cell_ps(float p, float q, float late,
                                         float Dv, bool valid) {
    const float m   = fminf(p, late);
    const float mid = fminf(q, fmaxf(p, late));
    const float top = fmaxf(q, late);
    const float s   = 1.0f + __expf(m - mid) + __expf(m - top);
    return valid ? (Dv + m - __logf(s)) : BIGV;
}

// ---------------------------------------------------------------------------
// Kernel 2: barrier-free warp-pipelined wavefront (release/acquire sync).
// 8 warps x 64 rows; thread t owns rows 2t+1, 2t+2. Early operand pairs are
// presorted one iteration ahead so only 2 min/max levels follow the shfl.
// ---------------------------------------------------------------------------
__global__ void __launch_bounds__(256, 1)
dp_kernel(const int* __restrict__ X_len, const int* __restrict__ Y_len,
          float* __restrict__ out) {
    __shared__ float edge[8][1032];    // edge[w][d] = R[d][64(w+1)]
    __shared__ int   prog[8];

    const int b    = blockIdx.x;
    const int tid  = threadIdx.x;
    const int w    = tid >> 5;
    const int lane = tid & 31;
    const int i_lo = 2 * tid + 1;
    const int i_hi = i_lo + 1;

    const int xl  = X_len[b];
    const int tot = xl + Y_len[b];
    const bool wantlo = (xl == i_lo);
    const bool wanthi = (xl == i_hi);
    const bool isl0  = (lane == 0);
    const bool isl31 = (lane == 31);

    if (tid < 8) { prog[tid] = 1; edge[tid][0] = BIGV; edge[tid][1] = BIGV; }
    __syncthreads();                    // the only CTA barrier

    const uint32_t prog_self = smem_u32(&prog[w]);
    const uint32_t prog_prev = smem_u32(&prog[(w == 0) ? 0 : w - 1]);

    const float2* Dp = (const float2*)(g_D + (size_t)b * NDPAD * NN) + tid;

    float2 Dc[TCH];
    #pragma unroll
    for (int k = 0; k < TCH; ++k) Dc[k] = Dp[(size_t)k * 256];

    // State: r1_lo/r1_hi = R[d-1] rows; presorted pairs
    //   (p_lo,q_lo) = sort(R[d-2][i_lo-1], R[d-1][i_lo])   for cur_lo
    //   (p_hi,q_hi) = sort(R[d-2][i_lo],   R[d-1][i_lo])   for cur_hi
    float r1_lo = BIGV, r1_hi = BIGV;
    float p_lo = (tid == 0) ? 0.0f : BIGV, q_lo = BIGV;
    float p_hi = BIGV, q_hi = BIGV;
    float res = 0.0f;

    for (int d0 = 2; d0 <= 1018; d0 += TCH) {
        // Prefetch next chunk's D.
        float2 Dn[TCH];
        #pragma unroll
        for (int k = 0; k < TCH; ++k)
            Dn[k] = Dp[(size_t)(d0 + 6 + k) * 256];

        // Acquire producer edges for this chunk.
        float e[TCH];
        if (w > 0) {
            const int needed = d0 + TCH - 2;
            while (ld_acquire_cta(prog_prev) < needed) { }
            #pragma unroll
            for (int k = 0; k < TCH; ++k) e[k] = edge[w - 1][d0 - 1 + k];
        } else {
            #pragma unroll
            for (int k = 0; k < TCH; ++k) e[k] = BIGV;
        }

        #pragma unroll
        for (int k = 0; k < TCH; ++k) {
            const int d = d0 + k;

            float tmp = __shfl_up_sync(0xffffffffu, r1_hi, 1);
            tmp = isl0 ? e[k] : tmp;

            const bool v_lo = (unsigned)(d - i_lo - 1) < (unsigned)MM;
            const bool v_hi = (unsigned)(d - i_hi - 1) < (unsigned)MM;

            const float cur_lo = cell_ps(p_lo, q_lo, tmp,   Dc[k].x, v_lo);
            const float cur_hi = cell_ps(p_hi, q_hi, r1_hi, Dc[k].y, v_hi);

            if (d == tot)
                res = wantlo ? cur_lo : (wanthi ? cur_hi : res);

            if (isl31) edge[w][d] = cur_hi;

            // Presort next iteration's early pairs.
            p_hi = fminf(r1_lo, cur_lo);   // sort(R[d-1][i_lo], R[d][i_lo])
            q_hi = fmaxf(r1_lo, cur_lo);
            p_lo = fminf(tmp, cur_lo);     // sort(R[d-1][i_lo-1], R[d][i_lo])
            q_lo = fmaxf(tmp, cur_lo);
            r1_lo = cur_lo;
            r1_hi = cur_hi;
        }

        if (w < 7 && isl31)
            st_release_cta(prog_self, d0 + TCH - 1);   // orders edge STS

        #pragma unroll
        for (int k = 0; k < TCH; ++k) Dc[k] = Dn[k];
    }

    if (wantlo | wanthi) out[b] = res;
}

// ---------------------------------------------------------------------------
extern "C" void kernel_launch(void* const* d_in, const int* in_sizes, int n_in,
                              void* d_out, int out_size) {
    const float* X     = (const float*)d_in[0];
    const float* Y     = (const float*)d_in[1];
    const int*   X_len = (const int*)d_in[2];
    const int*   Y_len = (const int*)d_in[3];
    float*       out   = (float*)d_out;

    dist_kernel<<<dim3(8, 8, BQ), 256>>>(X, Y);
    dp_kernel<<<BQ, 256>>>(X_len, Y_len, out);
}

// round 7
// speedup vs baseline: 3.2327x; 1.6818x over previous
#include <cuda_runtime.h>
#include <cstdint>

#define BQ    32
#define NN    512
#define MM    512
#define DFD   64
#define NDIAG 1023
#define NDPAD 1040          // padded (zero) so prefetch never clamps
#define TCH   8             // diagonals per chunk
#define NCHK  128           // chunks: d = 2 .. 1025

#define LOG2E 1.4426950408889634f
#define LN2   0.6931471805599453f
#define BIGS  1.4426950408889634e10f   // 1e10 * log2(e): self-maintaining under fp32

// Diagonal-major scaled distances: g_D[b][(i+j)][i] = log2e * ||x_i - y_j||^2.
// Zero-initialized; positions outside the valid band are never written.
__device__ float g_D[(size_t)BQ * NDPAD * NN];

// ---------------------------------------------------------------------------
__device__ __forceinline__ uint32_t smem_u32(const void* p) {
    return (uint32_t)__cvta_generic_to_shared(p);
}
__device__ __forceinline__ void st_release_cta(uint32_t addr, int v) {
    asm volatile("st.release.cta.shared.b32 [%0], %1;" :: "r"(addr), "r"(v) : "memory");
}
__device__ __forceinline__ int ld_acquire_cta(uint32_t addr) {
    int v;
    asm volatile("ld.acquire.cta.shared.b32 %0, [%1];" : "=r"(v) : "r"(addr) : "memory");
    return v;
}
__device__ __forceinline__ float ex2(float x) {
    float r; asm("ex2.approx.f32 %0, %1;" : "=f"(r) : "f"(x)); return r;
}
__device__ __forceinline__ float lg2(float x) {
    float r; asm("lg2.approx.f32 %0, %1;" : "=f"(r) : "f"(x)); return r;
}

// ---------------------------------------------------------------------------
// Kernel 1: pairwise squared distances (Gram form), scaled by log2e,
// written in diagonal-major layout.
// ---------------------------------------------------------------------------
__global__ void dist_kernel(const float* __restrict__ X,
                            const float* __restrict__ Y) {
    __shared__ float sm[2 * 64 * 65];
    __shared__ float xx[64], yy[64];
    float* Xs = sm;
    float* Ys = sm + 64 * 65;

    const int b  = blockIdx.z;
    const int i0 = blockIdx.y * 64;
    const int j0 = blockIdx.x * 64;
    const int tid = threadIdx.x;

    const float* Xb = X + ((size_t)b * NN + i0) * DFD;
    const float* Yb = Y + ((size_t)b * MM + j0) * DFD;

    #pragma unroll
    for (int idx = tid; idx < 64 * 64; idx += 256) {
        int r = idx >> 6, c = idx & 63;
        Xs[r * 65 + c] = Xb[r * 64 + c];
        Ys[r * 65 + c] = Yb[r * 64 + c];
    }
    __syncthreads();

    if (tid < 128) {
        const float* row = (tid < 64) ? &Xs[tid * 65] : &Ys[(tid - 64) * 65];
        float s = 0.f;
        #pragma unroll 8
        for (int k = 0; k < DFD; k++) s = fmaf(row[k], row[k], s);
        s *= LOG2E;
        if (tid < 64) xx[tid] = s; else yy[tid - 64] = s;
    }
    __syncthreads();

    const int ti = (tid >> 4) * 4;
    const int tj = (tid & 15) * 4;

    float acc[4][4];
    #pragma unroll
    for (int u = 0; u < 4; u++)
        #pragma unroll
        for (int v = 0; v < 4; v++) acc[u][v] = 0.f;

    #pragma unroll 4
    for (int k = 0; k < DFD; k++) {
        float xa[4], yb[4];
        #pragma unroll
        for (int u = 0; u < 4; u++) xa[u] = Xs[(ti + u) * 65 + k];
        #pragma unroll
        for (int v = 0; v < 4; v++) yb[v] = Ys[(tj + v) * 65 + k];
        #pragma unroll
        for (int u = 0; u < 4; u++)
            #pragma unroll
            for (int v = 0; v < 4; v++)
                acc[u][v] = fmaf(xa[u], yb[v], acc[u][v]);
    }
    __syncthreads();

    float* Dt = sm;                       // pitch 66 -> conflict-free diagonals
    #pragma unroll
    for (int u = 0; u < 4; u++)
        #pragma unroll
        for (int v = 0; v < 4; v++)
            Dt[(ti + u) * 66 + (tj + v)] =
                fmaf(-2.0f * LOG2E, acc[u][v], xx[ti + u] + yy[tj + v]);
    __syncthreads();

    const int warp = tid >> 5, lane = tid & 31;
    const size_t base = (size_t)b * NDPAD * NN;
    for (int dl = warp; dl < 127; dl += 8) {
        int lo = dl - 63; if (lo < 0) lo = 0;
        int hi = dl;      if (hi > 63) hi = 63;
        for (int ii = lo + lane; ii <= hi; ii += 32) {
            int gi = i0 + ii;
            int gj = j0 + dl - ii;
            g_D[base + (size_t)(gi + gj) * NN + gi] = Dt[ii * 66 + (dl - ii)];
        }
    }
}

// ---------------------------------------------------------------------------
// Soft-min cell, log2 domain, (p,q) presorted:
// cur = D' + m - log2(1 + 2^(m-mid) + 2^(m-top)).
// ---------------------------------------------------------------------------
__device__ __forceinline__ float cell(float p, float q, float late, float Dv) {
    const float m   = fminf(p, late);
    const float mid = fminf(q, fmaxf(p, late));
    const float top = fmaxf(q, late);
    const float s   = 1.0f + ex2(m - mid) + ex2(m - top);
    return Dv + m - lg2(s);
}

// ---------------------------------------------------------------------------
// Kernel 2: warp-pipelined wavefront, monotonic release/acquire handoff.
// 8 warps x 64 rows; thread t owns rows 2t+1, 2t+2. Intra-warp neighbor via
// SMEM lane ring; inter-warp via edge history + progress counters with
// nanosleep-backoff polling. D prefetched one chunk ahead; no validity SELs.
// ---------------------------------------------------------------------------
__global__ void __launch_bounds__(256, 1)
dp_kernel(const int* __restrict__ X_len, const int* __restrict__ Y_len,
          float* __restrict__ out) {
    __shared__ float edge[8][1032];    // edge[w][d] = R'[d][64(w+1)]
    __shared__ float nb[8][32];        // per-warp lane ring of cur_hi
    __shared__ int   prog[8];

    const int b    = blockIdx.x;
    const int tid  = threadIdx.x;
    const int w    = tid >> 5;
    const int lane = tid & 31;
    const int i_lo = 2 * tid + 1;
    const int i_hi = i_lo + 1;

    const int xl  = X_len[b];
    const int tot = xl + Y_len[b];
    const bool wantlo = (xl == i_lo);
    const bool wanthi = (xl == i_hi);
    const bool isl0  = (lane == 0);
    const bool isl31 = (lane == 31);
    const int  nlane = (lane == 0) ? 31 : lane - 1;

    if (tid < 16) edge[tid >> 1][tid & 1] = BIGS;
    if (tid < 8)  prog[tid] = 1;
    nb[w][lane] = BIGS;
    __syncthreads();                    // the only CTA barrier

    const uint32_t prog_self = smem_u32(&prog[w]);
    const uint32_t prog_prev = smem_u32(&prog[(w == 0) ? 0 : w - 1]);

    const float2* Dp = (const float2*)(g_D + (size_t)b * NDPAD * NN) + tid;

    float2 Dc[TCH];
    #pragma unroll
    for (int k = 0; k < TCH; ++k) Dc[k] = Dp[(size_t)k * 256];

    float r1_lo = BIGS, r1_hi = BIGS;
    float p_lo = (tid == 0) ? 0.0f : BIGS, q_lo = BIGS;
    float p_hi = BIGS, q_hi = BIGS;
    float res = 0.0f;

    for (int c = 0; c < NCHK; ++c) {
        const int d0 = 2 + TCH * c;

        // Prefetch next chunk's D (padded slots; tail reads hit zero pad).
        float2 Dn[TCH];
        #pragma unroll
        for (int k = 0; k < TCH; ++k)
            Dn[k] = Dp[(size_t)(TCH * (c + 1) + k) * 256];

        // Acquire producer edges for this chunk (monotonic counter, backoff).
        float e[TCH];
        if (w > 0) {
            const int needed = d0 + TCH - 2;
            while (ld_acquire_cta(prog_prev) < needed) __nanosleep(64);
            #pragma unroll
            for (int k = 0; k < TCH; ++k) e[k] = edge[w - 1][d0 - 1 + k];
        } else {
            #pragma unroll
            for (int k = 0; k < TCH; ++k) e[k] = BIGS;
        }

        #pragma unroll
        for (int k = 0; k < TCH; ++k) {
            const int d = d0 + k;

            // Neighbor's cur_hi from the previous diagonal (lane ring read
            // BEFORE this iteration's write).
            const float nbv = nb[w][nlane];

            // cur_hi has no LDS dependency -> compute & publish first.
            const float cur_hi = cell(p_hi, q_hi, r1_hi, Dc[k].y);
            nb[w][lane] = cur_hi;
            if (isl31) edge[w][d] = cur_hi;

            const float tmp = isl0 ? e[k] : nbv;
            const float cur_lo = cell(p_lo, q_lo, tmp, Dc[k].x);

            if (d == tot)
                res = wantlo ? cur_lo : (wanthi ? cur_hi : res);

            // Presort next iteration's early pairs.
            p_hi = fminf(r1_lo, cur_lo);
            q_hi = fmaxf(r1_lo, cur_lo);
            p_lo = fminf(tmp, cur_lo);
            q_lo = fmaxf(tmp, cur_lo);
            r1_lo = cur_lo;
            r1_hi = cur_hi;
        }

        if (w < 7 && isl31)
            st_release_cta(prog_self, d0 + TCH - 1);   // orders edge STS

        #pragma unroll
        for (int k = 0; k < TCH; ++k) Dc[k] = Dn[k];
    }

    if (wantlo | wanthi) out[b] = res * LN2;
}

// ---------------------------------------------------------------------------
extern "C" void kernel_launch(void* const* d_in, const int* in_sizes, int n_in,
                              void* d_out, int out_size) {
    const float* X     = (const float*)d_in[0];
    const float* Y     = (const float*)d_in[1];
    const int*   X_len = (const int*)d_in[2];
    const int*   Y_len = (const int*)d_in[3];
    float*       out   = (float*)d_out;

    dist_kernel<<<dim3(8, 8, BQ), 256>>>(X, Y);
    dp_kernel<<<BQ, 256>>>(X_len, Y_len, out);
}